// round 6
// baseline (speedup 1.0000x reference)
#include <cuda_runtime.h>
#include <cuda_bf16.h>
#include <math.h>
#include <stdint.h>

// ---------------------------------------------------------------------------
// TransformerBlock: B=8, N=1024, EMBED=768, HEADS=12, HEAD_DIM=64, HIDDEN=3072
// GEMMs: mma.sync.m16n8k8 tf32, 128x128 CTA tile, 4 warps x (64x64) warp
// tiles (1.0 LDS per MMA), 4-stage cp.async pipeline, fused epilogues.
// Weights fed as raw fp32 (HW truncates to tf32) — no rounding pass.
// Attention: fp32 flash kernel. LN: fp32 warp-reduce kernel.
// ---------------------------------------------------------------------------

#define B_      8
#define N_      1024
#define EMBED_  768
#define HEADS_  12
#define HD_     64
#define HIDDEN_ 3072
#define TOKENS_ (B_ * N_)          // 8192
#define QKVW_   (3 * EMBED_)       // 2304

// ---- scratch (static device globals: allocation-free) ----
__device__ float g_h   [TOKENS_ * EMBED_];
__device__ float g_qkv [TOKENS_ * QKVW_];
__device__ float g_ctx [TOKENS_ * EMBED_];
__device__ float g_x1  [TOKENS_ * EMBED_];
__device__ float g_h2  [TOKENS_ * EMBED_];
__device__ float g_ffn [TOKENS_ * HIDDEN_];

// ---------------------------------------------------------------------------
// helpers
// ---------------------------------------------------------------------------
__device__ __forceinline__ float tf32r(float x) {
    uint32_t u;
    asm("cvt.rna.tf32.f32 %0, %1;" : "=r"(u) : "f"(x));
    return __uint_as_float(u);
}
__device__ __forceinline__ uint32_t smem_u32(const void* p) {
    uint32_t a;
    asm("{ .reg .u64 t; cvta.to.shared.u64 t, %1; cvt.u32.u64 %0, t; }"
        : "=r"(a) : "l"(p));
    return a;
}
#define CP_ASYNC16(dst, src) \
    asm volatile("cp.async.cg.shared.global [%0], [%1], 16;" \
                 :: "r"(dst), "l"(src) : "memory")
#define CP_COMMIT()  asm volatile("cp.async.commit_group;" ::: "memory")
#define CP_WAIT2()   asm volatile("cp.async.wait_group 2;" ::: "memory")

__device__ __forceinline__ void mma_tf32(float* d, const uint32_t* a,
                                         const uint32_t* b) {
    asm volatile(
        "mma.sync.aligned.m16n8k8.row.col.f32.tf32.tf32.f32 "
        "{%0,%1,%2,%3}, {%4,%5,%6,%7}, {%8,%9}, {%0,%1,%2,%3};"
        : "+f"(d[0]), "+f"(d[1]), "+f"(d[2]), "+f"(d[3])
        : "r"(a[0]), "r"(a[1]), "r"(a[2]), "r"(a[3]), "r"(b[0]), "r"(b[1]));
}

// ---------------------------------------------------------------------------
// mma.sync tf32 GEMM: C[M,Nn] = A[M,K] @ W[Nn,K]^T + bias (+res / +gelu)
// EPI: 0 = bias, 1 = bias + residual, 2 = bias + exact GELU
// CTA 128x128, BK=16, 128 thr / 4 warps (2Mx2N, 64x64 per warp), 4 stages.
// smem row stride 20 floats -> conflict-free fragment LDS.
// ---------------------------------------------------------------------------
#define BK          16
#define ROWSTRIDE   20
#define MAT_FLOATS  (128 * ROWSTRIDE)          // 2560
#define STAGE_FLOATS (2 * MAT_FLOATS)          // A + W
#define STAGES      4
#define GEMM_DSMEM  (STAGES * STAGE_FLOATS * 4) // 81920 B

template <int EPI>
__global__ __launch_bounds__(128, 2) void mma_gemm(
    const float* __restrict__ A, const float* __restrict__ W,
    const float* __restrict__ bias, const float* __restrict__ res,
    float* __restrict__ C, int M, int Nn, int K)
{
    extern __shared__ float smf[];

    const int tid  = threadIdx.x;
    const int wid  = tid >> 5, lane = tid & 31;
    const int mBase = blockIdx.y * 128;
    const int nBase = blockIdx.x * 128;
    const int warp_m = wid & 1;        // 0..1
    const int warp_n = wid >> 1;       // 0..1
    const int g = lane >> 2;           // 0..7
    const int q = lane & 3;            // 0..3

    const uint32_t sm_base = smem_u32(smf);

    // per-thread cp.async mapping: 4 float4 per matrix per ktile
    // flat = tid + it*128 in [0,512): m = flat>>2, kq = (flat&3)*4
    int mL[4], kqL[4];
    #pragma unroll
    for (int it = 0; it < 4; it++) {
        int flat = tid + it * 128;
        mL[it]  = flat >> 2;
        kqL[it] = (flat & 3) << 2;
    }
    const float* Arow = A + (size_t)mBase * K;
    const float* Wrow = W + (size_t)nBase * K;

    const int nK = K / BK;

    // accumulators: 4 m-frags x 8 n-frags x 4 regs = 128
    float acc[4][8][4];
    #pragma unroll
    for (int i = 0; i < 4; i++)
        #pragma unroll
        for (int j = 0; j < 8; j++)
            #pragma unroll
            for (int r = 0; r < 4; r++) acc[i][j][r] = 0.f;

    // ---- prologue: issue 3 stages ----
    #pragma unroll
    for (int t = 0; t < 3; t++) {
        uint32_t sb = sm_base + (uint32_t)(t * STAGE_FLOATS) * 4u;
        int k0 = t * BK;
        #pragma unroll
        for (int it = 0; it < 4; it++) {
            uint32_t doff = (uint32_t)(mL[it] * ROWSTRIDE + kqL[it]) * 4u;
            CP_ASYNC16(sb + doff,                 Arow + (size_t)mL[it] * K + k0 + kqL[it]);
            CP_ASYNC16(sb + MAT_FLOATS * 4u + doff, Wrow + (size_t)mL[it] * K + k0 + kqL[it]);
        }
        CP_COMMIT();
    }

    // fragment row/col bases in smem
    int rA[4], cB[8];
    #pragma unroll
    for (int i = 0; i < 4; i++) rA[i] = (warp_m * 64 + i * 16 + g) * ROWSTRIDE;
    #pragma unroll
    for (int j = 0; j < 8; j++) cB[j] = (warp_n * 64 + j * 8 + g) * ROWSTRIDE;

    // ---- mainloop ----
    #pragma unroll 1
    for (int kt = 0; kt < nK; kt++) {
        CP_WAIT2();
        __syncthreads();

        const float* As = smf + (kt & 3) * STAGE_FLOATS;
        const uint32_t* Au = (const uint32_t*)As;
        const uint32_t* Wu = Au + MAT_FLOATS;

        #pragma unroll
        for (int ks = 0; ks < 2; ks++) {
            int k = ks * 8 + q;
            uint32_t a[4][4], b[8][2];
            #pragma unroll
            for (int i = 0; i < 4; i++) {
                a[i][0] = Au[rA[i] + k];
                a[i][1] = Au[rA[i] + 8 * ROWSTRIDE + k];
                a[i][2] = Au[rA[i] + k + 4];
                a[i][3] = Au[rA[i] + 8 * ROWSTRIDE + k + 4];
            }
            #pragma unroll
            for (int j = 0; j < 8; j++) {
                b[j][0] = Wu[cB[j] + k];
                b[j][1] = Wu[cB[j] + k + 4];
            }
            #pragma unroll
            for (int i = 0; i < 4; i++)
                #pragma unroll
                for (int j = 0; j < 8; j++)
                    mma_tf32(acc[i][j], a[i], b[j]);
        }
        __syncthreads();

        int ft = kt + 3;
        if (ft < nK) {
            uint32_t sb = sm_base + (uint32_t)((ft & 3) * STAGE_FLOATS) * 4u;
            int k0 = ft * BK;
            #pragma unroll
            for (int it = 0; it < 4; it++) {
                uint32_t doff = (uint32_t)(mL[it] * ROWSTRIDE + kqL[it]) * 4u;
                CP_ASYNC16(sb + doff,                 Arow + (size_t)mL[it] * K + k0 + kqL[it]);
                CP_ASYNC16(sb + MAT_FLOATS * 4u + doff, Wrow + (size_t)mL[it] * K + k0 + kqL[it]);
            }
        }
        CP_COMMIT();
    }

    // ---- epilogue ----
    #pragma unroll
    for (int i = 0; i < 4; i++) {
        int row0 = mBase + warp_m * 64 + i * 16 + g;
        #pragma unroll
        for (int j = 0; j < 8; j++) {
            int col = nBase + warp_n * 64 + j * 8 + q * 2;
            float bx = bias[col], by = bias[col + 1];

            #pragma unroll
            for (int half = 0; half < 2; half++) {
                int row = row0 + half * 8;
                float vx = acc[i][j][half * 2 + 0] + bx;
                float vy = acc[i][j][half * 2 + 1] + by;
                if (EPI == 1) {
                    float2 r2 = *(const float2*)(res + (size_t)row * Nn + col);
                    vx += r2.x; vy += r2.y;
                } else if (EPI == 2) {
                    vx = 0.5f * vx * (1.0f + erff(vx * 0.70710678118654752f));
                    vy = 0.5f * vy * (1.0f + erff(vy * 0.70710678118654752f));
                }
                float2 o; o.x = vx; o.y = vy;
                *(float2*)(C + (size_t)row * Nn + col) = o;
            }
        }
    }
}

// ---------------------------------------------------------------------------
// LayerNorm: one block per row of 768
// ---------------------------------------------------------------------------
__global__ __launch_bounds__(256) void ln_kernel(
    const float* __restrict__ x, const float* __restrict__ g,
    const float* __restrict__ b, float* __restrict__ out)
{
    int row = blockIdx.x;
    const float* xr = x + (size_t)row * EMBED_;
    float* orow = out + (size_t)row * EMBED_;
    int tid = threadIdx.x;

    float v0 = xr[tid], v1 = xr[tid + 256], v2 = xr[tid + 512];
    float s  = v0 + v1 + v2;
    float s2 = v0 * v0 + v1 * v1 + v2 * v2;

    #pragma unroll
    for (int o = 16; o > 0; o >>= 1) {
        s  += __shfl_xor_sync(0xffffffffu, s,  o);
        s2 += __shfl_xor_sync(0xffffffffu, s2, o);
    }
    __shared__ float sm1[8], sm2[8];
    int warp = tid >> 5, lane = tid & 31;
    if (lane == 0) { sm1[warp] = s; sm2[warp] = s2; }
    __syncthreads();
    float ts = 0.f, ts2 = 0.f;
    #pragma unroll
    for (int w = 0; w < 8; w++) { ts += sm1[w]; ts2 += sm2[w]; }

    float mu  = ts * (1.0f / EMBED_);
    float var = ts2 * (1.0f / EMBED_) - mu * mu;
    float inv = rsqrtf(var + 1e-5f);

    orow[tid      ] = (v0 - mu) * inv * g[tid      ] + b[tid      ];
    orow[tid + 256] = (v1 - mu) * inv * g[tid + 256] + b[tid + 256];
    orow[tid + 512] = (v2 - mu) * inv * g[tid + 512] + b[tid + 512];
}

// ---------------------------------------------------------------------------
// Flash attention (full, non-causal). grid = (N/64 q-tiles, B*HEADS).
// ---------------------------------------------------------------------------
#define FPAD 68
#define FLASH_SMEM (4 * 64 * FPAD * 4)

__global__ __launch_bounds__(256) void flash_kernel(
    const float* __restrict__ qkv, float* __restrict__ ctx)
{
    extern __shared__ float sm[];
    float* Qt = sm;
    float* Kt = Qt + 64 * FPAD;
    float* Vs = Kt + 64 * FPAD;
    float* Ps = Vs + 64 * FPAD;

    int tid = threadIdx.x;
    int qt  = blockIdx.x;
    int bh  = blockIdx.y;
    int bb  = bh / HEADS_, h = bh % HEADS_;

    const float* base = qkv + (size_t)bb * N_ * QKVW_ + h * HD_;

    #pragma unroll
    for (int p = 0; p < 16; p++) {
        int idx = p * 256 + tid;
        int row = idx >> 6, d = idx & 63;
        Qt[d * FPAD + row] = base[(size_t)(qt * 64 + row) * QKVW_ + d];
    }

    int ty = tid >> 4, tx = tid & 15;
    int rq = ty * 4, cq = tx * 4;

    float m_i[4], l_i[4], acc[4][4];
    #pragma unroll
    for (int i = 0; i < 4; i++) {
        m_i[i] = -1e30f; l_i[i] = 0.f;
        #pragma unroll
        for (int j = 0; j < 4; j++) acc[i][j] = 0.f;
    }

    for (int t = 0; t < 16; t++) {
        __syncthreads();
        #pragma unroll
        for (int p = 0; p < 16; p++) {
            int idx = p * 256 + tid;
            int row = idx >> 6, d = idx & 63;
            size_t gofs = (size_t)(t * 64 + row) * QKVW_ + d;
            Kt[d * FPAD + row] = base[gofs + EMBED_];
            Vs[row * FPAD + d] = base[gofs + 2 * EMBED_];
        }
        __syncthreads();

        float s[4][4];
        #pragma unroll
        for (int i = 0; i < 4; i++)
            #pragma unroll
            for (int j = 0; j < 4; j++) s[i][j] = 0.f;

        #pragma unroll 16
        for (int d = 0; d < 64; d++) {
            float4 qa = *(const float4*)&Qt[d * FPAD + rq];
            float4 kb = *(const float4*)&Kt[d * FPAD + cq];
            float aq[4] = {qa.x, qa.y, qa.z, qa.w};
            float bk[4] = {kb.x, kb.y, kb.z, kb.w};
            #pragma unroll
            for (int i = 0; i < 4; i++)
                #pragma unroll
                for (int j = 0; j < 4; j++)
                    s[i][j] = fmaf(aq[i], bk[j], s[i][j]);
        }

        #pragma unroll
        for (int i = 0; i < 4; i++) {
            #pragma unroll
            for (int j = 0; j < 4; j++) s[i][j] *= 0.125f;

            float mx = fmaxf(fmaxf(s[i][0], s[i][1]), fmaxf(s[i][2], s[i][3]));
            #pragma unroll
            for (int o = 1; o < 16; o <<= 1)
                mx = fmaxf(mx, __shfl_xor_sync(0xffffffffu, mx, o));
            float mnew = fmaxf(m_i[i], mx);
            float alpha = expf(m_i[i] - mnew);
            m_i[i] = mnew;

            float rs = 0.f;
            #pragma unroll
            for (int j = 0; j < 4; j++) {
                s[i][j] = expf(s[i][j] - mnew);
                rs += s[i][j];
            }
            #pragma unroll
            for (int o = 1; o < 16; o <<= 1)
                rs += __shfl_xor_sync(0xffffffffu, rs, o);

            l_i[i] = l_i[i] * alpha + rs;
            #pragma unroll
            for (int j = 0; j < 4; j++) acc[i][j] *= alpha;

            *(float4*)&Ps[(rq + i) * FPAD + cq] =
                make_float4(s[i][0], s[i][1], s[i][2], s[i][3]);
        }
        __syncthreads();

        #pragma unroll 16
        for (int k = 0; k < 64; k++) {
            float4 vv = *(const float4*)&Vs[k * FPAD + cq];
            #pragma unroll
            for (int i = 0; i < 4; i++) {
                float pa = Ps[(rq + i) * FPAD + k];
                acc[i][0] = fmaf(pa, vv.x, acc[i][0]);
                acc[i][1] = fmaf(pa, vv.y, acc[i][1]);
                acc[i][2] = fmaf(pa, vv.z, acc[i][2]);
                acc[i][3] = fmaf(pa, vv.w, acc[i][3]);
            }
        }
    }

    #pragma unroll
    for (int i = 0; i < 4; i++) {
        int token = bb * N_ + qt * 64 + rq + i;
        float inv = 1.0f / l_i[i];
        float4 o = make_float4(acc[i][0] * inv, acc[i][1] * inv,
                               acc[i][2] * inv, acc[i][3] * inv);
        *(float4*)(ctx + (size_t)token * EMBED_ + h * HD_ + cq) = o;
    }
}

// ---------------------------------------------------------------------------
// launch
// ---------------------------------------------------------------------------
extern "C" void kernel_launch(void* const* d_in, const int* in_sizes, int n_in,
                              void* d_out, int out_size)
{
    const float* x      = (const float*)d_in[0];
    const float* ln1_g  = (const float*)d_in[1];
    const float* ln1_b  = (const float*)d_in[2];
    const float* qkv_w  = (const float*)d_in[3];
    const float* qkv_b  = (const float*)d_in[4];
    const float* proj_w = (const float*)d_in[5];
    const float* proj_b = (const float*)d_in[6];
    const float* ln2_g  = (const float*)d_in[7];
    const float* ln2_b  = (const float*)d_in[8];
    const float* fc1_w  = (const float*)d_in[9];
    const float* fc1_b  = (const float*)d_in[10];
    const float* fc2_w  = (const float*)d_in[11];
    const float* fc2_b  = (const float*)d_in[12];
    float* out = (float*)d_out;

    float *h, *qkv, *ctx, *x1, *h2, *ffn;
    cudaGetSymbolAddress((void**)&h,   g_h);
    cudaGetSymbolAddress((void**)&qkv, g_qkv);
    cudaGetSymbolAddress((void**)&ctx, g_ctx);
    cudaGetSymbolAddress((void**)&x1,  g_x1);
    cudaGetSymbolAddress((void**)&h2,  g_h2);
    cudaGetSymbolAddress((void**)&ffn, g_ffn);

    cudaFuncSetAttribute(flash_kernel,
                         cudaFuncAttributeMaxDynamicSharedMemorySize, FLASH_SMEM);
    cudaFuncSetAttribute(mma_gemm<0>,
                         cudaFuncAttributeMaxDynamicSharedMemorySize, GEMM_DSMEM);
    cudaFuncSetAttribute(mma_gemm<1>,
                         cudaFuncAttributeMaxDynamicSharedMemorySize, GEMM_DSMEM);
    cudaFuncSetAttribute(mma_gemm<2>,
                         cudaFuncAttributeMaxDynamicSharedMemorySize, GEMM_DSMEM);

    // ln1
    ln_kernel<<<TOKENS_, 256>>>(x, ln1_g, ln1_b, h);
    // qkv = h @ qkv_w^T + b
    mma_gemm<0><<<dim3(QKVW_ / 128, TOKENS_ / 128), 128, GEMM_DSMEM>>>(
        h, qkv_w, qkv_b, nullptr, qkv, TOKENS_, QKVW_, EMBED_);
    // attention
    flash_kernel<<<dim3(N_ / 64, B_ * HEADS_), 256, FLASH_SMEM>>>(qkv, ctx);
    // x1 = x + ctx @ proj_w^T + b
    mma_gemm<1><<<dim3(EMBED_ / 128, TOKENS_ / 128), 128, GEMM_DSMEM>>>(
        ctx, proj_w, proj_b, x, x1, TOKENS_, EMBED_, EMBED_);
    // ln2
    ln_kernel<<<TOKENS_, 256>>>(x1, ln2_g, ln2_b, h2);
    // ffn = gelu(h2 @ fc1_w^T + b)
    mma_gemm<2><<<dim3(HIDDEN_ / 128, TOKENS_ / 128), 128, GEMM_DSMEM>>>(
        h2, fc1_w, fc1_b, nullptr, ffn, TOKENS_, HIDDEN_, EMBED_);
    // out = x1 + ffn @ fc2_w^T + b
    mma_gemm<1><<<dim3(EMBED_ / 128, TOKENS_ / 128), 128, GEMM_DSMEM>>>(
        ffn, fc2_w, fc2_b, x1, out, TOKENS_, EMBED_, HIDDEN_);
}

// round 7
// speedup vs baseline: 1.4693x; 1.4693x over previous
#include <cuda_runtime.h>
#include <cuda_bf16.h>
#include <math.h>
#include <stdint.h>

// ---------------------------------------------------------------------------
// TransformerBlock: B=8, N=1024, EMBED=768, HEADS=12, HEAD_DIM=64, HIDDEN=3072
// GEMMs: mma.sync.m16n8k8 tf32, 128x128 CTA tile, single-barrier cp.async
// pipeline with loads issued before compute.
// Attention: flash with tf32 mma.sync (Q frags register-resident, K/V
// double-buffered cp.async, P via smem round-trip). LN: fp32 warp-reduce.
// ---------------------------------------------------------------------------

#define B_      8
#define N_      1024
#define EMBED_  768
#define HEADS_  12
#define HD_     64
#define HIDDEN_ 3072
#define TOKENS_ (B_ * N_)          // 8192
#define QKVW_   (3 * EMBED_)       // 2304

// ---- scratch (static device globals: allocation-free) ----
__device__ float g_h   [TOKENS_ * EMBED_];
__device__ float g_qkv [TOKENS_ * QKVW_];
__device__ float g_ctx [TOKENS_ * EMBED_];
__device__ float g_x1  [TOKENS_ * EMBED_];
__device__ float g_h2  [TOKENS_ * EMBED_];
__device__ float g_ffn [TOKENS_ * HIDDEN_];

// ---------------------------------------------------------------------------
// helpers
// ---------------------------------------------------------------------------
__device__ __forceinline__ uint32_t smem_u32(const void* p) {
    uint32_t a;
    asm("{ .reg .u64 t; cvta.to.shared.u64 t, %1; cvt.u32.u64 %0, t; }"
        : "=r"(a) : "l"(p));
    return a;
}
#define CP_ASYNC16(dst, src) \
    asm volatile("cp.async.cg.shared.global [%0], [%1], 16;" \
                 :: "r"(dst), "l"(src) : "memory")
#define CP_COMMIT()  asm volatile("cp.async.commit_group;" ::: "memory")
#define CP_WAIT2()   asm volatile("cp.async.wait_group 2;" ::: "memory")
#define CP_WAIT1()   asm volatile("cp.async.wait_group 1;" ::: "memory")

__device__ __forceinline__ void mma_tf32(float* d, const uint32_t* a,
                                         const uint32_t* b) {
    asm volatile(
        "mma.sync.aligned.m16n8k8.row.col.f32.tf32.tf32.f32 "
        "{%0,%1,%2,%3}, {%4,%5,%6,%7}, {%8,%9}, {%0,%1,%2,%3};"
        : "+f"(d[0]), "+f"(d[1]), "+f"(d[2]), "+f"(d[3])
        : "r"(a[0]), "r"(a[1]), "r"(a[2]), "r"(a[3]), "r"(b[0]), "r"(b[1]));
}

// ---------------------------------------------------------------------------
// mma.sync tf32 GEMM: C[M,Nn] = A[M,K] @ W[Nn,K]^T + bias (+res / +gelu)
// EPI: 0 = bias, 1 = bias + residual, 2 = bias + exact GELU
// CTA 128x128, BK=16, 128 thr / 4 warps (2Mx2N, 64x64 per warp), 4 stages.
// Single barrier per ktile; loads for stage kt+3 issued before compute.
// ---------------------------------------------------------------------------
#define BK          16
#define ROWSTRIDE   20
#define MAT_FLOATS  (128 * ROWSTRIDE)          // 2560
#define STAGE_FLOATS (2 * MAT_FLOATS)          // A + W
#define STAGES      4
#define GEMM_DSMEM  (STAGES * STAGE_FLOATS * 4) // 81920 B

template <int EPI>
__global__ __launch_bounds__(128, 2) void mma_gemm(
    const float* __restrict__ A, const float* __restrict__ W,
    const float* __restrict__ bias, const float* __restrict__ res,
    float* __restrict__ C, int M, int Nn, int K)
{
    extern __shared__ float smf[];

    const int tid  = threadIdx.x;
    const int wid  = tid >> 5, lane = tid & 31;
    const int mBase = blockIdx.y * 128;
    const int nBase = blockIdx.x * 128;
    const int warp_m = wid & 1;
    const int warp_n = wid >> 1;
    const int g = lane >> 2;
    const int q = lane & 3;

    const uint32_t sm_base = smem_u32(smf);

    int mL[4], kqL[4];
    #pragma unroll
    for (int it = 0; it < 4; it++) {
        int flat = tid + it * 128;
        mL[it]  = flat >> 2;
        kqL[it] = (flat & 3) << 2;
    }
    const float* Arow = A + (size_t)mBase * K;
    const float* Wrow = W + (size_t)nBase * K;

    const int nK = K / BK;

    float acc[4][8][4];
    #pragma unroll
    for (int i = 0; i < 4; i++)
        #pragma unroll
        for (int j = 0; j < 8; j++)
            #pragma unroll
            for (int r = 0; r < 4; r++) acc[i][j][r] = 0.f;

    // ---- prologue: issue 3 stages ----
    #pragma unroll
    for (int t = 0; t < 3; t++) {
        uint32_t sb = sm_base + (uint32_t)(t * STAGE_FLOATS) * 4u;
        int k0 = t * BK;
        #pragma unroll
        for (int it = 0; it < 4; it++) {
            uint32_t doff = (uint32_t)(mL[it] * ROWSTRIDE + kqL[it]) * 4u;
            CP_ASYNC16(sb + doff,                   Arow + (size_t)mL[it] * K + k0 + kqL[it]);
            CP_ASYNC16(sb + MAT_FLOATS * 4u + doff, Wrow + (size_t)mL[it] * K + k0 + kqL[it]);
        }
        CP_COMMIT();
    }

    int rA[4], cB[8];
    #pragma unroll
    for (int i = 0; i < 4; i++) rA[i] = (warp_m * 64 + i * 16 + g) * ROWSTRIDE;
    #pragma unroll
    for (int j = 0; j < 8; j++) cB[j] = (warp_n * 64 + j * 8 + g) * ROWSTRIDE;

    // ---- mainloop: single barrier, loads issued before compute ----
    #pragma unroll 1
    for (int kt = 0; kt < nK; kt++) {
        CP_WAIT2();
        __syncthreads();

        int ft = kt + 3;
        if (ft < nK) {
            uint32_t sb = sm_base + (uint32_t)((ft & 3) * STAGE_FLOATS) * 4u;
            int k0 = ft * BK;
            #pragma unroll
            for (int it = 0; it < 4; it++) {
                uint32_t doff = (uint32_t)(mL[it] * ROWSTRIDE + kqL[it]) * 4u;
                CP_ASYNC16(sb + doff,                   Arow + (size_t)mL[it] * K + k0 + kqL[it]);
                CP_ASYNC16(sb + MAT_FLOATS * 4u + doff, Wrow + (size_t)mL[it] * K + k0 + kqL[it]);
            }
        }
        CP_COMMIT();

        const float* As = smf + (kt & 3) * STAGE_FLOATS;
        const uint32_t* Au = (const uint32_t*)As;
        const uint32_t* Wu = Au + MAT_FLOATS;

        #pragma unroll
        for (int ks = 0; ks < 2; ks++) {
            int k = ks * 8 + q;
            uint32_t a[4][4], b[8][2];
            #pragma unroll
            for (int i = 0; i < 4; i++) {
                a[i][0] = Au[rA[i] + k];
                a[i][1] = Au[rA[i] + 8 * ROWSTRIDE + k];
                a[i][2] = Au[rA[i] + k + 4];
                a[i][3] = Au[rA[i] + 8 * ROWSTRIDE + k + 4];
            }
            #pragma unroll
            for (int j = 0; j < 8; j++) {
                b[j][0] = Wu[cB[j] + k];
                b[j][1] = Wu[cB[j] + k + 4];
            }
            #pragma unroll
            for (int i = 0; i < 4; i++)
                #pragma unroll
                for (int j = 0; j < 8; j++)
                    mma_tf32(acc[i][j], a[i], b[j]);
        }
    }

    // ---- epilogue ----
    #pragma unroll
    for (int i = 0; i < 4; i++) {
        int row0 = mBase + warp_m * 64 + i * 16 + g;
        #pragma unroll
        for (int j = 0; j < 8; j++) {
            int col = nBase + warp_n * 64 + j * 8 + q * 2;
            float bx = bias[col], by = bias[col + 1];

            #pragma unroll
            for (int half = 0; half < 2; half++) {
                int row = row0 + half * 8;
                float vx = acc[i][j][half * 2 + 0] + bx;
                float vy = acc[i][j][half * 2 + 1] + by;
                if (EPI == 1) {
                    float2 r2 = *(const float2*)(res + (size_t)row * Nn + col);
                    vx += r2.x; vy += r2.y;
                } else if (EPI == 2) {
                    vx = 0.5f * vx * (1.0f + erff(vx * 0.70710678118654752f));
                    vy = 0.5f * vy * (1.0f + erff(vy * 0.70710678118654752f));
                }
                float2 o; o.x = vx; o.y = vy;
                *(float2*)(C + (size_t)row * Nn + col) = o;
            }
        }
    }
}

// ---------------------------------------------------------------------------
// LayerNorm: one block per row of 768
// ---------------------------------------------------------------------------
__global__ __launch_bounds__(256) void ln_kernel(
    const float* __restrict__ x, const float* __restrict__ g,
    const float* __restrict__ b, float* __restrict__ out)
{
    int row = blockIdx.x;
    const float* xr = x + (size_t)row * EMBED_;
    float* orow = out + (size_t)row * EMBED_;
    int tid = threadIdx.x;

    float v0 = xr[tid], v1 = xr[tid + 256], v2 = xr[tid + 512];
    float s  = v0 + v1 + v2;
    float s2 = v0 * v0 + v1 * v1 + v2 * v2;

    #pragma unroll
    for (int o = 16; o > 0; o >>= 1) {
        s  += __shfl_xor_sync(0xffffffffu, s,  o);
        s2 += __shfl_xor_sync(0xffffffffu, s2, o);
    }
    __shared__ float sm1[8], sm2[8];
    int warp = tid >> 5, lane = tid & 31;
    if (lane == 0) { sm1[warp] = s; sm2[warp] = s2; }
    __syncthreads();
    float ts = 0.f, ts2 = 0.f;
    #pragma unroll
    for (int w = 0; w < 8; w++) { ts += sm1[w]; ts2 += sm2[w]; }

    float mu  = ts * (1.0f / EMBED_);
    float var = ts2 * (1.0f / EMBED_) - mu * mu;
    float inv = rsqrtf(var + 1e-5f);

    orow[tid      ] = (v0 - mu) * inv * g[tid      ] + b[tid      ];
    orow[tid + 256] = (v1 - mu) * inv * g[tid + 256] + b[tid + 256];
    orow[tid + 512] = (v2 - mu) * inv * g[tid + 512] + b[tid + 512];
}

// ---------------------------------------------------------------------------
// Flash attention with tf32 mma.sync. grid = (N/64 q-tiles, B*HEADS), 128 thr.
// Per CTA: 64 q-rows; warp w owns q rows [w*16, w*16+16) (softmax warp-local).
// Q fragments register-resident (pre-scaled 1/8). K/V double-buffered cp.async.
// P (exp scores) round-trips through smem to become an A-operand for P@V.
// Smem strides: Q/P 68, K 68, V 72 -> conflict-free fragment LDS.
// ---------------------------------------------------------------------------
#define FB      64
#define TITERS  (N_ / FB)                    // 16
#define PS_OFF  0                            // 64x68 (Q staging, then P)
#define KS_OFF  (64 * 68)                    // 4352: 2 stages x 64x68
#define VS_OFF  (KS_OFF + 2 * 64 * 68)       // 13056: 2 stages x 64x72
#define FLASH_FLOATS (VS_OFF + 2 * 64 * 72)  // 22272
#define FLASH_SMEM   (FLASH_FLOATS * 4)      // 89088 B

__global__ __launch_bounds__(128, 2) void flash_mma_kernel(
    const float* __restrict__ qkv, float* __restrict__ ctx)
{
    extern __shared__ float sm[];
    const int tid  = threadIdx.x;
    const int wq   = tid >> 5, lane = tid & 31;
    const int g    = lane >> 2, q = lane & 3;
    const int qt   = blockIdx.x;
    const int bh   = blockIdx.y;
    const int bb   = bh / HEADS_, h = bh % HEADS_;

    const float* base = qkv + (size_t)bb * N_ * QKVW_ + h * HD_;
    const uint32_t smb = smem_u32(sm);

    // ---- prologue: group 0 = Q staging + KV stage 0; group 1 = KV stage 1 ----
    #pragma unroll
    for (int i = 0; i < 8; i++) {
        int c  = tid + 128 * i;              // 0..1023
        int r  = c >> 4;
        int c4 = (c & 15) << 2;
        const float* srow = base + (size_t)r * QKVW_;
        CP_ASYNC16(smb + (uint32_t)(KS_OFF + r * 68 + c4) * 4u, srow + EMBED_ + c4);
        CP_ASYNC16(smb + (uint32_t)(VS_OFF + r * 72 + c4) * 4u, srow + 2 * EMBED_ + c4);
        CP_ASYNC16(smb + (uint32_t)(PS_OFF + r * 68 + c4) * 4u,
                   base + (size_t)(qt * FB + r) * QKVW_ + c4);
    }
    CP_COMMIT();
    #pragma unroll
    for (int i = 0; i < 8; i++) {
        int c  = tid + 128 * i;
        int r  = c >> 4;
        int c4 = (c & 15) << 2;
        const float* srow = base + (size_t)(FB + r) * QKVW_;
        CP_ASYNC16(smb + (uint32_t)(KS_OFF + 4352 + r * 68 + c4) * 4u, srow + EMBED_ + c4);
        CP_ASYNC16(smb + (uint32_t)(VS_OFF + 4608 + r * 72 + c4) * 4u, srow + 2 * EMBED_ + c4);
    }
    CP_COMMIT();

    CP_WAIT1();              // group 0 (Q + KV0) done
    __syncthreads();

    // ---- Q fragments to registers, pre-scaled by HEAD_DIM^-0.5 = 0.125 ----
    const int r0 = wq * 16 + g;          // warp-local rows r0, r0+8
    uint32_t aQ[8][4];
    {
        const float* Qs = sm + PS_OFF;
        #pragma unroll
        for (int ks = 0; ks < 8; ks++) {
            int k = ks * 8 + q;
            aQ[ks][0] = __float_as_uint(Qs[r0 * 68 + k]           * 0.125f);
            aQ[ks][1] = __float_as_uint(Qs[(r0 + 8) * 68 + k]     * 0.125f);
            aQ[ks][2] = __float_as_uint(Qs[r0 * 68 + k + 4]       * 0.125f);
            aQ[ks][3] = __float_as_uint(Qs[(r0 + 8) * 68 + k + 4] * 0.125f);
        }
    }
    __syncthreads();         // Q staging now reusable as P buffer

    float accO[8][4];
    #pragma unroll
    for (int j = 0; j < 8; j++)
        #pragma unroll
        for (int r = 0; r < 4; r++) accO[j][r] = 0.f;
    float m0 = -1e30f, m1 = -1e30f, l0 = 0.f, l1 = 0.f;

    // ---- kv-tile loop ----
    #pragma unroll 1
    for (int t = 0; t < TITERS; t++) {
        if (t > 0) {
            CP_WAIT1();
            __syncthreads();
        }
        const uint32_t* Ku = (const uint32_t*)(sm + KS_OFF + (t & 1) * 4352);
        const uint32_t* Vu = (const uint32_t*)(sm + VS_OFF + (t & 1) * 4608);

        // S = Q K^T  (warp: 16 q-rows x 64 kv-cols)
        float s[8][4];
        #pragma unroll
        for (int j = 0; j < 8; j++)
            #pragma unroll
            for (int r = 0; r < 4; r++) s[j][r] = 0.f;

        #pragma unroll
        for (int ks = 0; ks < 8; ks++) {
            int k = ks * 8 + q;
            uint32_t b[8][2];
            #pragma unroll
            for (int j = 0; j < 8; j++) {
                b[j][0] = Ku[(j * 8 + g) * 68 + k];
                b[j][1] = Ku[(j * 8 + g) * 68 + k + 4];
            }
            #pragma unroll
            for (int j = 0; j < 8; j++)
                mma_tf32(s[j], aQ[ks], b[j]);
        }

        // ---- online softmax (rows r0, r0+8; quad lanes share a row) ----
        float mx0 = -1e30f, mx1 = -1e30f;
        #pragma unroll
        for (int j = 0; j < 8; j++) {
            mx0 = fmaxf(mx0, fmaxf(s[j][0], s[j][1]));
            mx1 = fmaxf(mx1, fmaxf(s[j][2], s[j][3]));
        }
        mx0 = fmaxf(mx0, __shfl_xor_sync(0xffffffffu, mx0, 1));
        mx0 = fmaxf(mx0, __shfl_xor_sync(0xffffffffu, mx0, 2));
        mx1 = fmaxf(mx1, __shfl_xor_sync(0xffffffffu, mx1, 1));
        mx1 = fmaxf(mx1, __shfl_xor_sync(0xffffffffu, mx1, 2));

        float mn0 = fmaxf(m0, mx0), mn1 = fmaxf(m1, mx1);
        float al0 = __expf(m0 - mn0), al1 = __expf(m1 - mn1);
        m0 = mn0; m1 = mn1;

        float rs0 = 0.f, rs1 = 0.f;
        #pragma unroll
        for (int j = 0; j < 8; j++) {
            s[j][0] = __expf(s[j][0] - mn0);
            s[j][1] = __expf(s[j][1] - mn0);
            s[j][2] = __expf(s[j][2] - mn1);
            s[j][3] = __expf(s[j][3] - mn1);
            rs0 += s[j][0] + s[j][1];
            rs1 += s[j][2] + s[j][3];
        }
        rs0 += __shfl_xor_sync(0xffffffffu, rs0, 1);
        rs0 += __shfl_xor_sync(0xffffffffu, rs0, 2);
        rs1 += __shfl_xor_sync(0xffffffffu, rs1, 1);
        rs1 += __shfl_xor_sync(0xffffffffu, rs1, 2);

        l0 = l0 * al0 + rs0;
        l1 = l1 * al1 + rs1;
        #pragma unroll
        for (int j = 0; j < 8; j++) {
            accO[j][0] *= al0; accO[j][1] *= al0;
            accO[j][2] *= al1; accO[j][3] *= al1;
        }

        // ---- store P to smem (warp-private rows), reload as A-frags ----
        float* Ps = sm + PS_OFF;
        #pragma unroll
        for (int j = 0; j < 8; j++) {
            float2 p01; p01.x = s[j][0]; p01.y = s[j][1];
            float2 p23; p23.x = s[j][2]; p23.y = s[j][3];
            *(float2*)&Ps[r0 * 68 + j * 8 + 2 * q]       = p01;
            *(float2*)&Ps[(r0 + 8) * 68 + j * 8 + 2 * q] = p23;
        }
        __syncwarp();

        const uint32_t* Pu = (const uint32_t*)Ps;
        #pragma unroll
        for (int ks = 0; ks < 8; ks++) {
            int k = ks * 8 + q;
            uint32_t aP[4];
            aP[0] = Pu[r0 * 68 + k];
            aP[1] = Pu[(r0 + 8) * 68 + k];
            aP[2] = Pu[r0 * 68 + k + 4];
            aP[3] = Pu[(r0 + 8) * 68 + k + 4];
            uint32_t b[8][2];
            #pragma unroll
            for (int j = 0; j < 8; j++) {
                b[j][0] = Vu[(ks * 8 + q) * 72 + j * 8 + g];
                b[j][1] = Vu[(ks * 8 + q + 4) * 72 + j * 8 + g];
            }
            #pragma unroll
            for (int j = 0; j < 8; j++)
                mma_tf32(accO[j], aP, b[j]);
        }

        __syncthreads();     // all reads of KV slot (t&1) done

        // ---- prefetch KV tile t+2 into slot (t&1) ----
        if (t + 2 < TITERS) {
            const float* src = base + (size_t)((t + 2) * FB) * QKVW_;
            uint32_t kd = smb + (uint32_t)(KS_OFF + (t & 1) * 4352) * 4u;
            uint32_t vd = smb + (uint32_t)(VS_OFF + (t & 1) * 4608) * 4u;
            #pragma unroll
            for (int i = 0; i < 8; i++) {
                int c  = tid + 128 * i;
                int r  = c >> 4;
                int c4 = (c & 15) << 2;
                const float* srow = src + (size_t)r * QKVW_;
                CP_ASYNC16(kd + (uint32_t)(r * 68 + c4) * 4u, srow + EMBED_ + c4);
                CP_ASYNC16(vd + (uint32_t)(r * 72 + c4) * 4u, srow + 2 * EMBED_ + c4);
            }
        }
        CP_COMMIT();
    }

    // ---- output: ctx[token][h*64 + d] ----
    float inv0 = 1.0f / l0, inv1 = 1.0f / l1;
    size_t tok0 = (size_t)(bb * N_ + qt * FB + r0);
    #pragma unroll
    for (int j = 0; j < 8; j++) {
        int col = h * HD_ + j * 8 + 2 * q;
        float2 o0; o0.x = accO[j][0] * inv0; o0.y = accO[j][1] * inv0;
        float2 o1; o1.x = accO[j][2] * inv1; o1.y = accO[j][3] * inv1;
        *(float2*)(ctx + tok0 * EMBED_ + col)       = o0;
        *(float2*)(ctx + (tok0 + 8) * EMBED_ + col) = o1;
    }
}

// ---------------------------------------------------------------------------
// launch
// ---------------------------------------------------------------------------
extern "C" void kernel_launch(void* const* d_in, const int* in_sizes, int n_in,
                              void* d_out, int out_size)
{
    const float* x      = (const float*)d_in[0];
    const float* ln1_g  = (const float*)d_in[1];
    const float* ln1_b  = (const float*)d_in[2];
    const float* qkv_w  = (const float*)d_in[3];
    const float* qkv_b  = (const float*)d_in[4];
    const float* proj_w = (const float*)d_in[5];
    const float* proj_b = (const float*)d_in[6];
    const float* ln2_g  = (const float*)d_in[7];
    const float* ln2_b  = (const float*)d_in[8];
    const float* fc1_w  = (const float*)d_in[9];
    const float* fc1_b  = (const float*)d_in[10];
    const float* fc2_w  = (const float*)d_in[11];
    const float* fc2_b  = (const float*)d_in[12];
    float* out = (float*)d_out;

    float *h, *qkv, *ctx, *x1, *h2, *ffn;
    cudaGetSymbolAddress((void**)&h,   g_h);
    cudaGetSymbolAddress((void**)&qkv, g_qkv);
    cudaGetSymbolAddress((void**)&ctx, g_ctx);
    cudaGetSymbolAddress((void**)&x1,  g_x1);
    cudaGetSymbolAddress((void**)&h2,  g_h2);
    cudaGetSymbolAddress((void**)&ffn, g_ffn);

    cudaFuncSetAttribute(flash_mma_kernel,
                         cudaFuncAttributeMaxDynamicSharedMemorySize, FLASH_SMEM);
    cudaFuncSetAttribute(mma_gemm<0>,
                         cudaFuncAttributeMaxDynamicSharedMemorySize, GEMM_DSMEM);
    cudaFuncSetAttribute(mma_gemm<1>,
                         cudaFuncAttributeMaxDynamicSharedMemorySize, GEMM_DSMEM);
    cudaFuncSetAttribute(mma_gemm<2>,
                         cudaFuncAttributeMaxDynamicSharedMemorySize, GEMM_DSMEM);

    // ln1
    ln_kernel<<<TOKENS_, 256>>>(x, ln1_g, ln1_b, h);
    // qkv = h @ qkv_w^T + b
    mma_gemm<0><<<dim3(QKVW_ / 128, TOKENS_ / 128), 128, GEMM_DSMEM>>>(
        h, qkv_w, qkv_b, nullptr, qkv, TOKENS_, QKVW_, EMBED_);
    // attention
    flash_mma_kernel<<<dim3(N_ / FB, B_ * HEADS_), 128, FLASH_SMEM>>>(qkv, ctx);
    // x1 = x + ctx @ proj_w^T + b
    mma_gemm<1><<<dim3(EMBED_ / 128, TOKENS_ / 128), 128, GEMM_DSMEM>>>(
        ctx, proj_w, proj_b, x, x1, TOKENS_, EMBED_, EMBED_);
    // ln2
    ln_kernel<<<TOKENS_, 256>>>(x1, ln2_g, ln2_b, h2);
    // ffn = gelu(h2 @ fc1_w^T + b)
    mma_gemm<2><<<dim3(HIDDEN_ / 128, TOKENS_ / 128), 128, GEMM_DSMEM>>>(
        h2, fc1_w, fc1_b, nullptr, ffn, TOKENS_, HIDDEN_, EMBED_);
    // out = x1 + ffn @ fc2_w^T + b
    mma_gemm<1><<<dim3(EMBED_ / 128, TOKENS_ / 128), 128, GEMM_DSMEM>>>(
        ffn, fc2_w, fc2_b, x1, out, TOKENS_, EMBED_, HIDDEN_);
}

// round 8
// speedup vs baseline: 2.2691x; 1.5443x over previous
#include <cuda_runtime.h>
#include <cuda_fp16.h>
#include <math.h>
#include <stdint.h>

// ---------------------------------------------------------------------------
// TransformerBlock: B=8, N=1024, EMBED=768, HEADS=12, HEAD_DIM=64, HIDDEN=3072
// GEMMs: mma.sync.m16n8k16 fp16 (fp32 accum). fp16 has the same 10-bit
// mantissa as tf32 -> same precision, 2x instruction density, half the smem
// and LDS traffic. Weights pre-converted to fp16; activations produced fp16.
// Attention: flash with tf32 mma.sync (reads fp32 qkv, writes fp16 ctx).
// ---------------------------------------------------------------------------

#define B_      8
#define N_      1024
#define EMBED_  768
#define HEADS_  12
#define HD_     64
#define HIDDEN_ 3072
#define TOKENS_ (B_ * N_)          // 8192
#define QKVW_   (3 * EMBED_)       // 2304

// ---- scratch (static device globals: allocation-free) ----
__device__ __half g_h16  [TOKENS_ * EMBED_];   // ln1 out (fp16)
__device__ float  g_qkv  [TOKENS_ * QKVW_];    // qkv (fp32, flash consumes)
__device__ __half g_ctx16[TOKENS_ * EMBED_];   // attention ctx (fp16)
__device__ float  g_x1   [TOKENS_ * EMBED_];   // after attn residual (fp32)
__device__ __half g_h216 [TOKENS_ * EMBED_];   // ln2 out (fp16)
__device__ __half g_ffn16[TOKENS_ * HIDDEN_];  // gelu out (fp16)
// fp16 weights
__device__ __half g_wq16 [QKVW_  * EMBED_];
__device__ __half g_wp16 [EMBED_ * EMBED_];
__device__ __half g_w116 [HIDDEN_ * EMBED_];
__device__ __half g_w216 [EMBED_ * HIDDEN_];

// ---------------------------------------------------------------------------
// helpers
// ---------------------------------------------------------------------------
__device__ __forceinline__ uint32_t smem_u32(const void* p) {
    uint32_t a;
    asm("{ .reg .u64 t; cvta.to.shared.u64 t, %1; cvt.u32.u64 %0, t; }"
        : "=r"(a) : "l"(p));
    return a;
}
#define CP_ASYNC16(dst, src) \
    asm volatile("cp.async.cg.shared.global [%0], [%1], 16;" \
                 :: "r"(dst), "l"(src) : "memory")
#define CP_COMMIT()  asm volatile("cp.async.commit_group;" ::: "memory")
#define CP_WAIT2()   asm volatile("cp.async.wait_group 2;" ::: "memory")
#define CP_WAIT1()   asm volatile("cp.async.wait_group 1;" ::: "memory")

__device__ __forceinline__ void mma_f16(float* d, const uint32_t* a,
                                        const uint32_t* b) {
    asm volatile(
        "mma.sync.aligned.m16n8k16.row.col.f32.f16.f16.f32 "
        "{%0,%1,%2,%3}, {%4,%5,%6,%7}, {%8,%9}, {%0,%1,%2,%3};"
        : "+f"(d[0]), "+f"(d[1]), "+f"(d[2]), "+f"(d[3])
        : "r"(a[0]), "r"(a[1]), "r"(a[2]), "r"(a[3]), "r"(b[0]), "r"(b[1]));
}
__device__ __forceinline__ void mma_tf32(float* d, const uint32_t* a,
                                         const uint32_t* b) {
    asm volatile(
        "mma.sync.aligned.m16n8k8.row.col.f32.tf32.tf32.f32 "
        "{%0,%1,%2,%3}, {%4,%5,%6,%7}, {%8,%9}, {%0,%1,%2,%3};"
        : "+f"(d[0]), "+f"(d[1]), "+f"(d[2]), "+f"(d[3])
        : "r"(a[0]), "r"(a[1]), "r"(a[2]), "r"(a[3]), "r"(b[0]), "r"(b[1]));
}

// ---------------------------------------------------------------------------
// fp32 -> fp16 convert (weights), 4 elems/thread
// ---------------------------------------------------------------------------
__global__ __launch_bounds__(256) void f2h_kernel(
    const float* __restrict__ in, __half* __restrict__ out, int n4)
{
    int i = blockIdx.x * blockDim.x + threadIdx.x;
    if (i < n4) {
        float4 v = ((const float4*)in)[i];
        __half2 h0 = __floats2half2_rn(v.x, v.y);
        __half2 h1 = __floats2half2_rn(v.z, v.w);
        uint2 o;
        o.x = *(uint32_t*)&h0;
        o.y = *(uint32_t*)&h1;
        ((uint2*)out)[i] = o;
    }
}

// ---------------------------------------------------------------------------
// fp16 mma GEMM: C[M,Nn] = A[M,K] @ W[Nn,K]^T + bias (+res / +gelu)
// EPI: 0 = bias (fp32 out), 1 = bias + residual (fp32 out),
//      2 = bias + exact GELU (fp16 out)
// CTA 128x128, BK=32 halves, 128 thr / 4 warps (64x64 per warp), 4 stages.
// smem row stride 40 halves (20 words) -> conflict-free fragment LDS.
// ---------------------------------------------------------------------------
#define BK          32
#define RSH         40                          // row stride in halves
#define RSW         (RSH / 2)                   // 20 words
#define MAT_HALVES  (128 * RSH)                 // 5120
#define STAGE_HALVES (2 * MAT_HALVES)           // 10240
#define STAGES      4
#define GEMM_DSMEM  (STAGES * STAGE_HALVES * 2) // 81920 B

template <int EPI>
__global__ __launch_bounds__(128, 2) void mma_gemm(
    const __half* __restrict__ A, const __half* __restrict__ W,
    const float* __restrict__ bias, const float* __restrict__ res,
    void* __restrict__ Cv, int M, int Nn, int K)
{
    extern __shared__ __half smh[];

    const int tid  = threadIdx.x;
    const int wid  = tid >> 5, lane = tid & 31;
    const int mBase = blockIdx.y * 128;
    const int nBase = blockIdx.x * 128;
    const int warp_m = wid & 1;
    const int warp_n = wid >> 1;
    const int g = lane >> 2;
    const int q = lane & 3;

    const uint32_t sm_base = smem_u32(smh);

    // cp.async mapping: per matrix per ktile 128 rows x 64 B = 512 chunks;
    // 4 chunks per thread per matrix. flat = tid + it*128.
    int rL[4], cL[4];
    #pragma unroll
    for (int it = 0; it < 4; it++) {
        int flat = tid + it * 128;
        rL[it] = flat >> 2;          // 0..127
        cL[it] = (flat & 3) << 3;    // halves: 0,8,16,24
    }
    const __half* Arow = A + (size_t)mBase * K;
    const __half* Wrow = W + (size_t)nBase * K;

    const int nK = K / BK;

    float acc[4][8][4];
    #pragma unroll
    for (int i = 0; i < 4; i++)
        #pragma unroll
        for (int j = 0; j < 8; j++)
            #pragma unroll
            for (int r = 0; r < 4; r++) acc[i][j][r] = 0.f;

    // ---- prologue: issue 3 stages ----
    #pragma unroll
    for (int t = 0; t < 3; t++) {
        uint32_t sb = sm_base + (uint32_t)(t * STAGE_HALVES) * 2u;
        int k0 = t * BK;
        #pragma unroll
        for (int it = 0; it < 4; it++) {
            uint32_t doff = (uint32_t)(rL[it] * RSH + cL[it]) * 2u;
            CP_ASYNC16(sb + doff,                   Arow + (size_t)rL[it] * K + k0 + cL[it]);
            CP_ASYNC16(sb + MAT_HALVES * 2u + doff, Wrow + (size_t)rL[it] * K + k0 + cL[it]);
        }
        CP_COMMIT();
    }

    int rA[4], cB[8];
    #pragma unroll
    for (int i = 0; i < 4; i++) rA[i] = (warp_m * 64 + i * 16 + g) * RSW;
    #pragma unroll
    for (int j = 0; j < 8; j++) cB[j] = (warp_n * 64 + j * 8 + g) * RSW;

    // ---- mainloop: single barrier, prefetch before compute ----
    #pragma unroll 1
    for (int kt = 0; kt < nK; kt++) {
        CP_WAIT2();
        __syncthreads();

        int ft = kt + 3;
        if (ft < nK) {
            uint32_t sb = sm_base + (uint32_t)((ft & 3) * STAGE_HALVES) * 2u;
            int k0 = ft * BK;
            #pragma unroll
            for (int it = 0; it < 4; it++) {
                uint32_t doff = (uint32_t)(rL[it] * RSH + cL[it]) * 2u;
                CP_ASYNC16(sb + doff,                   Arow + (size_t)rL[it] * K + k0 + cL[it]);
                CP_ASYNC16(sb + MAT_HALVES * 2u + doff, Wrow + (size_t)rL[it] * K + k0 + cL[it]);
            }
        }
        CP_COMMIT();

        const uint32_t* Au = (const uint32_t*)(smh + (kt & 3) * STAGE_HALVES);
        const uint32_t* Wu = Au + MAT_HALVES / 2;

        #pragma unroll
        for (int ks = 0; ks < 2; ks++) {       // two k16 steps per ktile
            int kw = ks * 8 + q;               // word offset within row
            uint32_t a[4][4], b[8][2];
            #pragma unroll
            for (int i = 0; i < 4; i++) {
                a[i][0] = Au[rA[i] + kw];
                a[i][1] = Au[rA[i] + 8 * RSW + kw];
                a[i][2] = Au[rA[i] + kw + 4];
                a[i][3] = Au[rA[i] + 8 * RSW + kw + 4];
            }
            #pragma unroll
            for (int j = 0; j < 8; j++) {
                b[j][0] = Wu[cB[j] + kw];
                b[j][1] = Wu[cB[j] + kw + 4];
            }
            #pragma unroll
            for (int i = 0; i < 4; i++)
                #pragma unroll
                for (int j = 0; j < 8; j++)
                    mma_f16(acc[i][j], a[i], b[j]);
        }
    }

    // ---- epilogue ----
    float*  Cf = (float*)Cv;
    __half* Ch = (__half*)Cv;
    #pragma unroll
    for (int i = 0; i < 4; i++) {
        int row0 = mBase + warp_m * 64 + i * 16 + g;
        #pragma unroll
        for (int j = 0; j < 8; j++) {
            int col = nBase + warp_n * 64 + j * 8 + q * 2;
            float bx = bias[col], by = bias[col + 1];

            #pragma unroll
            for (int half = 0; half < 2; half++) {
                int row = row0 + half * 8;
                float vx = acc[i][j][half * 2 + 0] + bx;
                float vy = acc[i][j][half * 2 + 1] + by;
                if (EPI == 1) {
                    float2 r2 = *(const float2*)(res + (size_t)row * Nn + col);
                    vx += r2.x; vy += r2.y;
                    float2 o; o.x = vx; o.y = vy;
                    *(float2*)(Cf + (size_t)row * Nn + col) = o;
                } else if (EPI == 2) {
                    vx = 0.5f * vx * (1.0f + erff(vx * 0.70710678118654752f));
                    vy = 0.5f * vy * (1.0f + erff(vy * 0.70710678118654752f));
                    *(__half2*)(Ch + (size_t)row * Nn + col) =
                        __floats2half2_rn(vx, vy);
                } else {
                    float2 o; o.x = vx; o.y = vy;
                    *(float2*)(Cf + (size_t)row * Nn + col) = o;
                }
            }
        }
    }
}

// ---------------------------------------------------------------------------
// LayerNorm: one block per row of 768, fp16 output (feeds GEMM A)
// ---------------------------------------------------------------------------
__global__ __launch_bounds__(256) void ln_kernel(
    const float* __restrict__ x, const float* __restrict__ g,
    const float* __restrict__ b, __half* __restrict__ out)
{
    int row = blockIdx.x;
    const float* xr = x + (size_t)row * EMBED_;
    __half* orow = out + (size_t)row * EMBED_;
    int tid = threadIdx.x;

    float v0 = xr[tid], v1 = xr[tid + 256], v2 = xr[tid + 512];
    float s  = v0 + v1 + v2;
    float s2 = v0 * v0 + v1 * v1 + v2 * v2;

    #pragma unroll
    for (int o = 16; o > 0; o >>= 1) {
        s  += __shfl_xor_sync(0xffffffffu, s,  o);
        s2 += __shfl_xor_sync(0xffffffffu, s2, o);
    }
    __shared__ float sm1[8], sm2[8];
    int warp = tid >> 5, lane = tid & 31;
    if (lane == 0) { sm1[warp] = s; sm2[warp] = s2; }
    __syncthreads();
    float ts = 0.f, ts2 = 0.f;
    #pragma unroll
    for (int w = 0; w < 8; w++) { ts += sm1[w]; ts2 += sm2[w]; }

    float mu  = ts * (1.0f / EMBED_);
    float var = ts2 * (1.0f / EMBED_) - mu * mu;
    float inv = rsqrtf(var + 1e-5f);

    orow[tid      ] = __float2half_rn((v0 - mu) * inv * g[tid      ] + b[tid      ]);
    orow[tid + 256] = __float2half_rn((v1 - mu) * inv * g[tid + 256] + b[tid + 256]);
    orow[tid + 512] = __float2half_rn((v2 - mu) * inv * g[tid + 512] + b[tid + 512]);
}

// ---------------------------------------------------------------------------
// Flash attention with tf32 mma.sync (unchanged core), fp16 ctx output.
// grid = (N/64 q-tiles, B*HEADS), 128 threads.
// ---------------------------------------------------------------------------
#define FB      64
#define TITERS  (N_ / FB)                    // 16
#define PS_OFF  0                            // 64x68 (Q staging, then P)
#define KS_OFF  (64 * 68)                    // 2 stages x 64x68
#define VS_OFF  (KS_OFF + 2 * 64 * 68)       // 2 stages x 64x72
#define FLASH_FLOATS (VS_OFF + 2 * 64 * 72)
#define FLASH_SMEM   (FLASH_FLOATS * 4)      // 89088 B

__global__ __launch_bounds__(128, 2) void flash_mma_kernel(
    const float* __restrict__ qkv, __half* __restrict__ ctx)
{
    extern __shared__ float sm[];
    const int tid  = threadIdx.x;
    const int wq   = tid >> 5, lane = tid & 31;
    const int g    = lane >> 2, q = lane & 3;
    const int qt   = blockIdx.x;
    const int bh   = blockIdx.y;
    const int bb   = bh / HEADS_, h = bh % HEADS_;

    const float* base = qkv + (size_t)bb * N_ * QKVW_ + h * HD_;
    const uint32_t smb = smem_u32(sm);

    #pragma unroll
    for (int i = 0; i < 8; i++) {
        int c  = tid + 128 * i;
        int r  = c >> 4;
        int c4 = (c & 15) << 2;
        const float* srow = base + (size_t)r * QKVW_;
        CP_ASYNC16(smb + (uint32_t)(KS_OFF + r * 68 + c4) * 4u, srow + EMBED_ + c4);
        CP_ASYNC16(smb + (uint32_t)(VS_OFF + r * 72 + c4) * 4u, srow + 2 * EMBED_ + c4);
        CP_ASYNC16(smb + (uint32_t)(PS_OFF + r * 68 + c4) * 4u,
                   base + (size_t)(qt * FB + r) * QKVW_ + c4);
    }
    CP_COMMIT();
    #pragma unroll
    for (int i = 0; i < 8; i++) {
        int c  = tid + 128 * i;
        int r  = c >> 4;
        int c4 = (c & 15) << 2;
        const float* srow = base + (size_t)(FB + r) * QKVW_;
        CP_ASYNC16(smb + (uint32_t)(KS_OFF + 4352 + r * 68 + c4) * 4u, srow + EMBED_ + c4);
        CP_ASYNC16(smb + (uint32_t)(VS_OFF + 4608 + r * 72 + c4) * 4u, srow + 2 * EMBED_ + c4);
    }
    CP_COMMIT();

    CP_WAIT1();
    __syncthreads();

    const int r0 = wq * 16 + g;
    uint32_t aQ[8][4];
    {
        const float* Qs = sm + PS_OFF;
        #pragma unroll
        for (int ks = 0; ks < 8; ks++) {
            int k = ks * 8 + q;
            aQ[ks][0] = __float_as_uint(Qs[r0 * 68 + k]           * 0.125f);
            aQ[ks][1] = __float_as_uint(Qs[(r0 + 8) * 68 + k]     * 0.125f);
            aQ[ks][2] = __float_as_uint(Qs[r0 * 68 + k + 4]       * 0.125f);
            aQ[ks][3] = __float_as_uint(Qs[(r0 + 8) * 68 + k + 4] * 0.125f);
        }
    }
    __syncthreads();

    float accO[8][4];
    #pragma unroll
    for (int j = 0; j < 8; j++)
        #pragma unroll
        for (int r = 0; r < 4; r++) accO[j][r] = 0.f;
    float m0 = -1e30f, m1 = -1e30f, l0 = 0.f, l1 = 0.f;

    #pragma unroll 1
    for (int t = 0; t < TITERS; t++) {
        if (t > 0) {
            CP_WAIT1();
            __syncthreads();
        }
        const uint32_t* Ku = (const uint32_t*)(sm + KS_OFF + (t & 1) * 4352);
        const uint32_t* Vu = (const uint32_t*)(sm + VS_OFF + (t & 1) * 4608);

        float s[8][4];
        #pragma unroll
        for (int j = 0; j < 8; j++)
            #pragma unroll
            for (int r = 0; r < 4; r++) s[j][r] = 0.f;

        #pragma unroll
        for (int ks = 0; ks < 8; ks++) {
            int k = ks * 8 + q;
            uint32_t b[8][2];
            #pragma unroll
            for (int j = 0; j < 8; j++) {
                b[j][0] = Ku[(j * 8 + g) * 68 + k];
                b[j][1] = Ku[(j * 8 + g) * 68 + k + 4];
            }
            #pragma unroll
            for (int j = 0; j < 8; j++)
                mma_tf32(s[j], aQ[ks], b[j]);
        }

        float mx0 = -1e30f, mx1 = -1e30f;
        #pragma unroll
        for (int j = 0; j < 8; j++) {
            mx0 = fmaxf(mx0, fmaxf(s[j][0], s[j][1]));
            mx1 = fmaxf(mx1, fmaxf(s[j][2], s[j][3]));
        }
        mx0 = fmaxf(mx0, __shfl_xor_sync(0xffffffffu, mx0, 1));
        mx0 = fmaxf(mx0, __shfl_xor_sync(0xffffffffu, mx0, 2));
        mx1 = fmaxf(mx1, __shfl_xor_sync(0xffffffffu, mx1, 1));
        mx1 = fmaxf(mx1, __shfl_xor_sync(0xffffffffu, mx1, 2));

        float mn0 = fmaxf(m0, mx0), mn1 = fmaxf(m1, mx1);
        float al0 = __expf(m0 - mn0), al1 = __expf(m1 - mn1);
        m0 = mn0; m1 = mn1;

        float rs0 = 0.f, rs1 = 0.f;
        #pragma unroll
        for (int j = 0; j < 8; j++) {
            s[j][0] = __expf(s[j][0] - mn0);
            s[j][1] = __expf(s[j][1] - mn0);
            s[j][2] = __expf(s[j][2] - mn1);
            s[j][3] = __expf(s[j][3] - mn1);
            rs0 += s[j][0] + s[j][1];
            rs1 += s[j][2] + s[j][3];
        }
        rs0 += __shfl_xor_sync(0xffffffffu, rs0, 1);
        rs0 += __shfl_xor_sync(0xffffffffu, rs0, 2);
        rs1 += __shfl_xor_sync(0xffffffffu, rs1, 1);
        rs1 += __shfl_xor_sync(0xffffffffu, rs1, 2);

        l0 = l0 * al0 + rs0;
        l1 = l1 * al1 + rs1;
        #pragma unroll
        for (int j = 0; j < 8; j++) {
            accO[j][0] *= al0; accO[j][1] *= al0;
            accO[j][2] *= al1; accO[j][3] *= al1;
        }

        float* Ps = sm + PS_OFF;
        #pragma unroll
        for (int j = 0; j < 8; j++) {
            float2 p01; p01.x = s[j][0]; p01.y = s[j][1];
            float2 p23; p23.x = s[j][2]; p23.y = s[j][3];
            *(float2*)&Ps[r0 * 68 + j * 8 + 2 * q]       = p01;
            *(float2*)&Ps[(r0 + 8) * 68 + j * 8 + 2 * q] = p23;
        }
        __syncwarp();

        const uint32_t* Pu = (const uint32_t*)Ps;
        #pragma unroll
        for (int ks = 0; ks < 8; ks++) {
            int k = ks * 8 + q;
            uint32_t aP[4];
            aP[0] = Pu[r0 * 68 + k];
            aP[1] = Pu[(r0 + 8) * 68 + k];
            aP[2] = Pu[r0 * 68 + k + 4];
            aP[3] = Pu[(r0 + 8) * 68 + k + 4];
            uint32_t b[8][2];
            #pragma unroll
            for (int j = 0; j < 8; j++) {
                b[j][0] = Vu[(ks * 8 + q) * 72 + j * 8 + g];
                b[j][1] = Vu[(ks * 8 + q + 4) * 72 + j * 8 + g];
            }
            #pragma unroll
            for (int j = 0; j < 8; j++)
                mma_tf32(accO[j], aP, b[j]);
        }

        __syncthreads();

        if (t + 2 < TITERS) {
            const float* src = base + (size_t)((t + 2) * FB) * QKVW_;
            uint32_t kd = smb + (uint32_t)(KS_OFF + (t & 1) * 4352) * 4u;
            uint32_t vd = smb + (uint32_t)(VS_OFF + (t & 1) * 4608) * 4u;
            #pragma unroll
            for (int i = 0; i < 8; i++) {
                int c  = tid + 128 * i;
                int r  = c >> 4;
                int c4 = (c & 15) << 2;
                const float* srow = src + (size_t)r * QKVW_;
                CP_ASYNC16(kd + (uint32_t)(r * 68 + c4) * 4u, srow + EMBED_ + c4);
                CP_ASYNC16(vd + (uint32_t)(r * 72 + c4) * 4u, srow + 2 * EMBED_ + c4);
            }
        }
        CP_COMMIT();
    }

    // ---- output (fp16 ctx): ctx[token][h*64 + d] ----
    float inv0 = 1.0f / l0, inv1 = 1.0f / l1;
    size_t tok0 = (size_t)(bb * N_ + qt * FB + r0);
    #pragma unroll
    for (int j = 0; j < 8; j++) {
        int col = h * HD_ + j * 8 + 2 * q;
        *(__half2*)(ctx + tok0 * EMBED_ + col) =
            __floats2half2_rn(accO[j][0] * inv0, accO[j][1] * inv0);
        *(__half2*)(ctx + (tok0 + 8) * EMBED_ + col) =
            __floats2half2_rn(accO[j][2] * inv1, accO[j][3] * inv1);
    }
}

// ---------------------------------------------------------------------------
// launch
// ---------------------------------------------------------------------------
extern "C" void kernel_launch(void* const* d_in, const int* in_sizes, int n_in,
                              void* d_out, int out_size)
{
    const float* x      = (const float*)d_in[0];
    const float* ln1_g  = (const float*)d_in[1];
    const float* ln1_b  = (const float*)d_in[2];
    const float* qkv_w  = (const float*)d_in[3];
    const float* qkv_b  = (const float*)d_in[4];
    const float* proj_w = (const float*)d_in[5];
    const float* proj_b = (const float*)d_in[6];
    const float* ln2_g  = (const float*)d_in[7];
    const float* ln2_b  = (const float*)d_in[8];
    const float* fc1_w  = (const float*)d_in[9];
    const float* fc1_b  = (const float*)d_in[10];
    const float* fc2_w  = (const float*)d_in[11];
    const float* fc2_b  = (const float*)d_in[12];
    float* out = (float*)d_out;

    __half *h16, *ctx16, *h216, *ffn16, *wq16, *wp16, *w116, *w216;
    float *qkv, *x1;
    cudaGetSymbolAddress((void**)&h16,   g_h16);
    cudaGetSymbolAddress((void**)&qkv,   g_qkv);
    cudaGetSymbolAddress((void**)&ctx16, g_ctx16);
    cudaGetSymbolAddress((void**)&x1,    g_x1);
    cudaGetSymbolAddress((void**)&h216,  g_h216);
    cudaGetSymbolAddress((void**)&ffn16, g_ffn16);
    cudaGetSymbolAddress((void**)&wq16,  g_wq16);
    cudaGetSymbolAddress((void**)&wp16,  g_wp16);
    cudaGetSymbolAddress((void**)&w116,  g_w116);
    cudaGetSymbolAddress((void**)&w216,  g_w216);

    cudaFuncSetAttribute(flash_mma_kernel,
                         cudaFuncAttributeMaxDynamicSharedMemorySize, FLASH_SMEM);
    cudaFuncSetAttribute(mma_gemm<0>,
                         cudaFuncAttributeMaxDynamicSharedMemorySize, GEMM_DSMEM);
    cudaFuncSetAttribute(mma_gemm<1>,
                         cudaFuncAttributeMaxDynamicSharedMemorySize, GEMM_DSMEM);
    cudaFuncSetAttribute(mma_gemm<2>,
                         cudaFuncAttributeMaxDynamicSharedMemorySize, GEMM_DSMEM);

    // weights -> fp16 (once per replay; cheap)
    {
        int n4;
        n4 = QKVW_ * EMBED_ / 4;
        f2h_kernel<<<(n4 + 255) / 256, 256>>>(qkv_w, wq16, n4);
        n4 = EMBED_ * EMBED_ / 4;
        f2h_kernel<<<(n4 + 255) / 256, 256>>>(proj_w, wp16, n4);
        n4 = HIDDEN_ * EMBED_ / 4;
        f2h_kernel<<<(n4 + 255) / 256, 256>>>(fc1_w, w116, n4);
        n4 = EMBED_ * HIDDEN_ / 4;
        f2h_kernel<<<(n4 + 255) / 256, 256>>>(fc2_w, w216, n4);
    }

    // ln1 (fp16 out)
    ln_kernel<<<TOKENS_, 256>>>(x, ln1_g, ln1_b, h16);
    // qkv = h @ qkv_w^T + b  (fp32 out for flash)
    mma_gemm<0><<<dim3(QKVW_ / 128, TOKENS_ / 128), 128, GEMM_DSMEM>>>(
        h16, wq16, qkv_b, nullptr, qkv, TOKENS_, QKVW_, EMBED_);
    // attention (fp16 ctx out)
    flash_mma_kernel<<<dim3(N_ / FB, B_ * HEADS_), 128, FLASH_SMEM>>>(qkv, ctx16);
    // x1 = x + ctx @ proj_w^T + b  (fp32 out)
    mma_gemm<1><<<dim3(EMBED_ / 128, TOKENS_ / 128), 128, GEMM_DSMEM>>>(
        ctx16, wp16, proj_b, x, x1, TOKENS_, EMBED_, EMBED_);
    // ln2 (fp16 out)
    ln_kernel<<<TOKENS_, 256>>>(x1, ln2_g, ln2_b, h216);
    // ffn = gelu(h2 @ fc1_w^T + b)  (fp16 out)
    mma_gemm<2><<<dim3(HIDDEN_ / 128, TOKENS_ / 128), 128, GEMM_DSMEM>>>(
        h216, w116, fc1_b, nullptr, ffn16, TOKENS_, HIDDEN_, EMBED_);
    // out = x1 + ffn @ fc2_w^T + b  (fp32 out)
    mma_gemm<1><<<dim3(EMBED_ / 128, TOKENS_ / 128), 128, GEMM_DSMEM>>>(
        ffn16, w216, fc2_b, x1, out, TOKENS_, EMBED_, HIDDEN_);
}

// round 9
// speedup vs baseline: 2.9729x; 1.3102x over previous
#include <cuda_runtime.h>
#include <cuda_fp16.h>
#include <math.h>
#include <stdint.h>

// ---------------------------------------------------------------------------
// TransformerBlock: B=8, N=1024, EMBED=768, HEADS=12, HEAD_DIM=64, HIDDEN=3072
// GEMMs: mma.sync.m16n8k16 fp16 + ldmatrix.x4 operand loads.
// Attention: full-fp16 flash (QK^T and P@V both m16n8k16; K via ldmatrix,
// V via ldmatrix.trans; P fp16; softmax fp32).
// ---------------------------------------------------------------------------

#define B_      8
#define N_      1024
#define EMBED_  768
#define HEADS_  12
#define HD_     64
#define HIDDEN_ 3072
#define TOKENS_ (B_ * N_)          // 8192
#define QKVW_   (3 * EMBED_)       // 2304

// ---- scratch (static device globals: allocation-free) ----
__device__ __half g_h16  [TOKENS_ * EMBED_];   // ln1 out
__device__ __half g_qkv16[TOKENS_ * QKVW_];    // qkv (fp16)
__device__ __half g_ctx16[TOKENS_ * EMBED_];   // attention ctx
__device__ float  g_x1   [TOKENS_ * EMBED_];   // after attn residual
__device__ __half g_h216 [TOKENS_ * EMBED_];   // ln2 out
__device__ __half g_ffn16[TOKENS_ * HIDDEN_];  // gelu out
// fp16 weights
__device__ __half g_wq16 [QKVW_  * EMBED_];
__device__ __half g_wp16 [EMBED_ * EMBED_];
__device__ __half g_w116 [HIDDEN_ * EMBED_];
__device__ __half g_w216 [EMBED_ * HIDDEN_];

// ---------------------------------------------------------------------------
// helpers
// ---------------------------------------------------------------------------
__device__ __forceinline__ uint32_t smem_u32(const void* p) {
    uint32_t a;
    asm("{ .reg .u64 t; cvta.to.shared.u64 t, %1; cvt.u32.u64 %0, t; }"
        : "=r"(a) : "l"(p));
    return a;
}
#define CP_ASYNC16(dst, src) \
    asm volatile("cp.async.cg.shared.global [%0], [%1], 16;" \
                 :: "r"(dst), "l"(src) : "memory")
#define CP_COMMIT()  asm volatile("cp.async.commit_group;" ::: "memory")
#define CP_WAIT2()   asm volatile("cp.async.wait_group 2;" ::: "memory")
#define CP_WAIT1()   asm volatile("cp.async.wait_group 1;" ::: "memory")

#define LDSM_X4(r0, r1, r2, r3, addr) \
    asm volatile("ldmatrix.sync.aligned.m8n8.x4.shared.b16 {%0,%1,%2,%3}, [%4];" \
                 : "=r"(r0), "=r"(r1), "=r"(r2), "=r"(r3) : "r"(addr))
#define LDSM_X4T(r0, r1, r2, r3, addr) \
    asm volatile("ldmatrix.sync.aligned.m8n8.x4.trans.shared.b16 {%0,%1,%2,%3}, [%4];" \
                 : "=r"(r0), "=r"(r1), "=r"(r2), "=r"(r3) : "r"(addr))

__device__ __forceinline__ void mma_f16(float* d, const uint32_t* a,
                                        const uint32_t* b) {
    asm volatile(
        "mma.sync.aligned.m16n8k16.row.col.f32.f16.f16.f32 "
        "{%0,%1,%2,%3}, {%4,%5,%6,%7}, {%8,%9}, {%0,%1,%2,%3};"
        : "+f"(d[0]), "+f"(d[1]), "+f"(d[2]), "+f"(d[3])
        : "r"(a[0]), "r"(a[1]), "r"(a[2]), "r"(a[3]), "r"(b[0]), "r"(b[1]));
}

// ---------------------------------------------------------------------------
// fp32 -> fp16 convert (weights)
// ---------------------------------------------------------------------------
__global__ __launch_bounds__(256) void f2h_kernel(
    const float* __restrict__ in, __half* __restrict__ out, int n4)
{
    int i = blockIdx.x * blockDim.x + threadIdx.x;
    if (i < n4) {
        float4 v = ((const float4*)in)[i];
        __half2 h0 = __floats2half2_rn(v.x, v.y);
        __half2 h1 = __floats2half2_rn(v.z, v.w);
        uint2 o;
        o.x = *(uint32_t*)&h0;
        o.y = *(uint32_t*)&h1;
        ((uint2*)out)[i] = o;
    }
}

// ---------------------------------------------------------------------------
// fp16 mma GEMM with ldmatrix: C = A @ W^T + bias (+res / +gelu)
// EPI: 0 = bias (fp16 out), 1 = bias + residual (fp32 out),
//      2 = bias + exact GELU (fp16 out)
// CTA 128x128, BK=32 halves, 128 thr / 4 warps (64x64/warp), 4 stages.
// ---------------------------------------------------------------------------
#define BK          32
#define RSH         40                          // row stride in halves
#define MAT_HALVES  (128 * RSH)                 // 5120
#define STAGE_HALVES (2 * MAT_HALVES)           // 10240
#define STAGES      4
#define GEMM_DSMEM  (STAGES * STAGE_HALVES * 2) // 81920 B

template <int EPI>
__global__ __launch_bounds__(128, 2) void mma_gemm(
    const __half* __restrict__ A, const __half* __restrict__ W,
    const float* __restrict__ bias, const float* __restrict__ res,
    void* __restrict__ Cv, int M, int Nn, int K)
{
    extern __shared__ __half smh[];

    const int tid  = threadIdx.x;
    const int wid  = tid >> 5, lane = tid & 31;
    const int mBase = blockIdx.y * 128;
    const int nBase = blockIdx.x * 128;
    const int warp_m = wid & 1;
    const int warp_n = wid >> 1;
    const int g = lane >> 2;
    const int q = lane & 3;
    const int m3 = lane >> 3, r8 = lane & 7;    // ldmatrix lane roles

    const uint32_t sm_base = smem_u32(smh);

    // cp.async mapping: 4 chunks (16B) per thread per matrix per ktile
    int rL[4], cL[4];
    #pragma unroll
    for (int it = 0; it < 4; it++) {
        int flat = tid + it * 128;
        rL[it] = flat >> 2;
        cL[it] = (flat & 3) << 3;    // halves
    }
    const __half* Arow = A + (size_t)mBase * K;
    const __half* Wrow = W + (size_t)nBase * K;

    const int nK = K / BK;

    // ldmatrix byte offsets (within a stage's A / W matrix)
    uint32_t aoff[4], boff[4];
    #pragma unroll
    for (int i = 0; i < 4; i++)
        aoff[i] = (uint32_t)(((warp_m * 64 + i * 16 + (m3 & 1) * 8 + r8) * RSH
                              + (m3 >> 1) * 8) * 2);
    #pragma unroll
    for (int p = 0; p < 4; p++)
        boff[p] = (uint32_t)(((warp_n * 64 + (2 * p + (m3 >> 1)) * 8 + r8) * RSH
                              + (m3 & 1) * 8) * 2);

    float acc[4][8][4];
    #pragma unroll
    for (int i = 0; i < 4; i++)
        #pragma unroll
        for (int j = 0; j < 8; j++)
            #pragma unroll
            for (int r = 0; r < 4; r++) acc[i][j][r] = 0.f;

    // ---- prologue: 3 stages ----
    #pragma unroll
    for (int t = 0; t < 3; t++) {
        uint32_t sb = sm_base + (uint32_t)(t * STAGE_HALVES) * 2u;
        int k0 = t * BK;
        #pragma unroll
        for (int it = 0; it < 4; it++) {
            uint32_t doff = (uint32_t)(rL[it] * RSH + cL[it]) * 2u;
            CP_ASYNC16(sb + doff,                   Arow + (size_t)rL[it] * K + k0 + cL[it]);
            CP_ASYNC16(sb + MAT_HALVES * 2u + doff, Wrow + (size_t)rL[it] * K + k0 + cL[it]);
        }
        CP_COMMIT();
    }

    // ---- mainloop ----
    #pragma unroll 1
    for (int kt = 0; kt < nK; kt++) {
        CP_WAIT2();
        __syncthreads();

        int ft = kt + 3;
        if (ft < nK) {
            uint32_t sb = sm_base + (uint32_t)((ft & 3) * STAGE_HALVES) * 2u;
            int k0 = ft * BK;
            #pragma unroll
            for (int it = 0; it < 4; it++) {
                uint32_t doff = (uint32_t)(rL[it] * RSH + cL[it]) * 2u;
                CP_ASYNC16(sb + doff,                   Arow + (size_t)rL[it] * K + k0 + cL[it]);
                CP_ASYNC16(sb + MAT_HALVES * 2u + doff, Wrow + (size_t)rL[it] * K + k0 + cL[it]);
            }
        }
        CP_COMMIT();

        uint32_t sA = sm_base + (uint32_t)((kt & 3) * STAGE_HALVES) * 2u;
        uint32_t sW = sA + MAT_HALVES * 2u;

        #pragma unroll
        for (int ks = 0; ks < 2; ks++) {
            uint32_t ko = (uint32_t)(ks * 32);   // 16 halves
            uint32_t a[4][4], b[8][2];
            #pragma unroll
            for (int i = 0; i < 4; i++)
                LDSM_X4(a[i][0], a[i][1], a[i][2], a[i][3], sA + aoff[i] + ko);
            #pragma unroll
            for (int p = 0; p < 4; p++)
                LDSM_X4(b[2*p][0], b[2*p][1], b[2*p+1][0], b[2*p+1][1],
                        sW + boff[p] + ko);
            #pragma unroll
            for (int i = 0; i < 4; i++)
                #pragma unroll
                for (int j = 0; j < 8; j++)
                    mma_f16(acc[i][j], a[i], b[j]);
        }
    }

    // ---- epilogue ----
    float*  Cf = (float*)Cv;
    __half* Ch = (__half*)Cv;
    #pragma unroll
    for (int i = 0; i < 4; i++) {
        int row0 = mBase + warp_m * 64 + i * 16 + g;
        #pragma unroll
        for (int j = 0; j < 8; j++) {
            int col = nBase + warp_n * 64 + j * 8 + q * 2;
            float bx = bias[col], by = bias[col + 1];

            #pragma unroll
            for (int half = 0; half < 2; half++) {
                int row = row0 + half * 8;
                float vx = acc[i][j][half * 2 + 0] + bx;
                float vy = acc[i][j][half * 2 + 1] + by;
                if (EPI == 1) {
                    float2 r2 = *(const float2*)(res + (size_t)row * Nn + col);
                    vx += r2.x; vy += r2.y;
                    float2 o; o.x = vx; o.y = vy;
                    *(float2*)(Cf + (size_t)row * Nn + col) = o;
                } else if (EPI == 2) {
                    vx = 0.5f * vx * (1.0f + erff(vx * 0.70710678118654752f));
                    vy = 0.5f * vy * (1.0f + erff(vy * 0.70710678118654752f));
                    *(__half2*)(Ch + (size_t)row * Nn + col) =
                        __floats2half2_rn(vx, vy);
                } else {
                    *(__half2*)(Ch + (size_t)row * Nn + col) =
                        __floats2half2_rn(vx, vy);
                }
            }
        }
    }
}

// ---------------------------------------------------------------------------
// LayerNorm: one block per row of 768, fp16 output
// ---------------------------------------------------------------------------
__global__ __launch_bounds__(256) void ln_kernel(
    const float* __restrict__ x, const float* __restrict__ g,
    const float* __restrict__ b, __half* __restrict__ out)
{
    int row = blockIdx.x;
    const float* xr = x + (size_t)row * EMBED_;
    __half* orow = out + (size_t)row * EMBED_;
    int tid = threadIdx.x;

    float v0 = xr[tid], v1 = xr[tid + 256], v2 = xr[tid + 512];
    float s  = v0 + v1 + v2;
    float s2 = v0 * v0 + v1 * v1 + v2 * v2;

    #pragma unroll
    for (int o = 16; o > 0; o >>= 1) {
        s  += __shfl_xor_sync(0xffffffffu, s,  o);
        s2 += __shfl_xor_sync(0xffffffffu, s2, o);
    }
    __shared__ float sm1[8], sm2[8];
    int warp = tid >> 5, lane = tid & 31;
    if (lane == 0) { sm1[warp] = s; sm2[warp] = s2; }
    __syncthreads();
    float ts = 0.f, ts2 = 0.f;
    #pragma unroll
    for (int w = 0; w < 8; w++) { ts += sm1[w]; ts2 += sm2[w]; }

    float mu  = ts * (1.0f / EMBED_);
    float var = ts2 * (1.0f / EMBED_) - mu * mu;
    float inv = rsqrtf(var + 1e-5f);

    orow[tid      ] = __float2half_rn((v0 - mu) * inv * g[tid      ] + b[tid      ]);
    orow[tid + 256] = __float2half_rn((v1 - mu) * inv * g[tid + 256] + b[tid + 256]);
    orow[tid + 512] = __float2half_rn((v2 - mu) * inv * g[tid + 512] + b[tid + 512]);
}

// ---------------------------------------------------------------------------
// Flash attention, full fp16 operands (fp32 softmax + accum).
// grid = (N/64 q-tiles, B*HEADS), 128 threads / 4 warps; warp owns 16 q-rows.
// smem (halves, stride 72): Q/P 64x72 @0; K 2x(64x72) @4608; V 2x @13824.
// ---------------------------------------------------------------------------
#define FB      64
#define TITERS  (N_ / FB)                    // 16
#define FRS     72                           // halves per row
#define FRW     (FRS / 2)                    // 36 words
#define QP_OFF  0
#define K_OFF   (64 * FRS)                   // 4608
#define V_OFF   (3 * 64 * FRS)               // 13824
#define KSTG    (64 * FRS)                   // stage stride (halves)
#define FLASH_SMEM (5 * 64 * FRS * 2)        // 46080 B

__global__ __launch_bounds__(128, 2) void flash_mma_kernel(
    const __half* __restrict__ qkv, __half* __restrict__ ctx)
{
    extern __shared__ __half fsm[];
    const int tid  = threadIdx.x;
    const int wq   = tid >> 5, lane = tid & 31;
    const int g    = lane >> 2, q = lane & 3;
    const int m3   = lane >> 3, r8 = lane & 7;
    const int qt   = blockIdx.x;
    const int bh   = blockIdx.y;
    const int bb   = bh / HEADS_, h = bh % HEADS_;

    const __half* base = qkv + (size_t)bb * N_ * QKVW_ + h * HD_;
    const uint32_t smb = smem_u32(fsm);

    // ldmatrix byte offsets (within one K / V stage)
    uint32_t koff[4], voff[4];
    #pragma unroll
    for (int p = 0; p < 4; p++) {
        koff[p] = (uint32_t)((((2 * p + (m3 >> 1)) * 8 + r8) * FRS + (m3 & 1) * 8) * 2);
        voff[p] = (uint32_t)((((m3 & 1) * 8 + r8) * FRS + (2 * p + (m3 >> 1)) * 8) * 2);
    }

    // ---- prologue: group0 = Q + K0 + V0; group1 = K1 + V1 ----
    #pragma unroll
    for (int i = 0; i < 4; i++) {
        int c   = tid + 128 * i;           // 0..511
        int r   = c >> 3;                  // row 0..63
        int c16 = (c & 7) << 3;            // halves 0..56
        const __half* srow = base + (size_t)r * QKVW_;
        CP_ASYNC16(smb + (uint32_t)(K_OFF + r * FRS + c16) * 2u, srow + EMBED_ + c16);
        CP_ASYNC16(smb + (uint32_t)(V_OFF + r * FRS + c16) * 2u, srow + 2 * EMBED_ + c16);
        CP_ASYNC16(smb + (uint32_t)(QP_OFF + r * FRS + c16) * 2u,
                   base + (size_t)(qt * FB + r) * QKVW_ + c16);
    }
    CP_COMMIT();
    #pragma unroll
    for (int i = 0; i < 4; i++) {
        int c   = tid + 128 * i;
        int r   = c >> 3;
        int c16 = (c & 7) << 3;
        const __half* srow = base + (size_t)(FB + r) * QKVW_;
        CP_ASYNC16(smb + (uint32_t)(K_OFF + KSTG + r * FRS + c16) * 2u, srow + EMBED_ + c16);
        CP_ASYNC16(smb + (uint32_t)(V_OFF + KSTG + r * FRS + c16) * 2u, srow + 2 * EMBED_ + c16);
    }
    CP_COMMIT();

    CP_WAIT1();
    __syncthreads();

    // ---- Q fragments (4 ksteps x 4 regs), scaled by 0.125 (exact) ----
    const int r0 = wq * 16 + g;
    const __half2 hs = __float2half2_rn(0.125f);
    uint32_t aQ[4][4];
    {
        const uint32_t* Qw = (const uint32_t*)(fsm + QP_OFF);
        #pragma unroll
        for (int ks = 0; ks < 4; ks++) {
            aQ[ks][0] = Qw[r0 * FRW + ks * 8 + q];
            aQ[ks][1] = Qw[(r0 + 8) * FRW + ks * 8 + q];
            aQ[ks][2] = Qw[r0 * FRW + ks * 8 + 4 + q];
            aQ[ks][3] = Qw[(r0 + 8) * FRW + ks * 8 + 4 + q];
            #pragma unroll
            for (int r = 0; r < 4; r++) {
                __half2 v = *(__half2*)&aQ[ks][r];
                v = __hmul2(v, hs);
                aQ[ks][r] = *(uint32_t*)&v;
            }
        }
    }
    __syncthreads();   // Q region becomes P buffer

    float accO[8][4];
    #pragma unroll
    for (int j = 0; j < 8; j++)
        #pragma unroll
        for (int r = 0; r < 4; r++) accO[j][r] = 0.f;
    float m0 = -1e30f, m1 = -1e30f, l0 = 0.f, l1 = 0.f;

    // ---- kv-tile loop ----
    #pragma unroll 1
    for (int t = 0; t < TITERS; t++) {
        if (t > 0) {
            CP_WAIT1();
            __syncthreads();
        }
        uint32_t kb = smb + (uint32_t)(K_OFF + (t & 1) * KSTG) * 2u;
        uint32_t vb = smb + (uint32_t)(V_OFF + (t & 1) * KSTG) * 2u;

        // S = Q K^T
        float s[8][4];
        #pragma unroll
        for (int j = 0; j < 8; j++)
            #pragma unroll
            for (int r = 0; r < 4; r++) s[j][r] = 0.f;

        #pragma unroll
        for (int ks = 0; ks < 4; ks++) {
            uint32_t b[8][2];
            #pragma unroll
            for (int p = 0; p < 4; p++)
                LDSM_X4(b[2*p][0], b[2*p][1], b[2*p+1][0], b[2*p+1][1],
                        kb + koff[p] + ks * 32);
            #pragma unroll
            for (int j = 0; j < 8; j++)
                mma_f16(s[j], aQ[ks], b[j]);
        }

        // ---- online softmax (rows r0, r0+8) ----
        float mx0 = -1e30f, mx1 = -1e30f;
        #pragma unroll
        for (int j = 0; j < 8; j++) {
            mx0 = fmaxf(mx0, fmaxf(s[j][0], s[j][1]));
            mx1 = fmaxf(mx1, fmaxf(s[j][2], s[j][3]));
        }
        mx0 = fmaxf(mx0, __shfl_xor_sync(0xffffffffu, mx0, 1));
        mx0 = fmaxf(mx0, __shfl_xor_sync(0xffffffffu, mx0, 2));
        mx1 = fmaxf(mx1, __shfl_xor_sync(0xffffffffu, mx1, 1));
        mx1 = fmaxf(mx1, __shfl_xor_sync(0xffffffffu, mx1, 2));

        float mn0 = fmaxf(m0, mx0), mn1 = fmaxf(m1, mx1);
        float al0 = __expf(m0 - mn0), al1 = __expf(m1 - mn1);
        m0 = mn0; m1 = mn1;

        float rs0 = 0.f, rs1 = 0.f;
        #pragma unroll
        for (int j = 0; j < 8; j++) {
            s[j][0] = __expf(s[j][0] - mn0);
            s[j][1] = __expf(s[j][1] - mn0);
            s[j][2] = __expf(s[j][2] - mn1);
            s[j][3] = __expf(s[j][3] - mn1);
            rs0 += s[j][0] + s[j][1];
            rs1 += s[j][2] + s[j][3];
        }
        rs0 += __shfl_xor_sync(0xffffffffu, rs0, 1);
        rs0 += __shfl_xor_sync(0xffffffffu, rs0, 2);
        rs1 += __shfl_xor_sync(0xffffffffu, rs1, 1);
        rs1 += __shfl_xor_sync(0xffffffffu, rs1, 2);

        l0 = l0 * al0 + rs0;
        l1 = l1 * al1 + rs1;
        #pragma unroll
        for (int j = 0; j < 8; j++) {
            accO[j][0] *= al0; accO[j][1] *= al0;
            accO[j][2] *= al1; accO[j][3] *= al1;
        }

        // ---- P (fp16) to warp-private smem rows, reload as A-frags ----
        __half* Ps = fsm + QP_OFF;
        #pragma unroll
        for (int j = 0; j < 8; j++) {
            *(__half2*)&Ps[r0 * FRS + j * 8 + 2 * q] =
                __floats2half2_rn(s[j][0], s[j][1]);
            *(__half2*)&Ps[(r0 + 8) * FRS + j * 8 + 2 * q] =
                __floats2half2_rn(s[j][2], s[j][3]);
        }
        __syncwarp();

        const uint32_t* Pw = (const uint32_t*)(fsm + QP_OFF);
        #pragma unroll
        for (int ks = 0; ks < 4; ks++) {       // kv blocks of 16
            uint32_t aP[4];
            aP[0] = Pw[r0 * FRW + ks * 8 + q];
            aP[1] = Pw[(r0 + 8) * FRW + ks * 8 + q];
            aP[2] = Pw[r0 * FRW + ks * 8 + 4 + q];
            aP[3] = Pw[(r0 + 8) * FRW + ks * 8 + 4 + q];
            uint32_t b[8][2];
            #pragma unroll
            for (int p = 0; p < 4; p++)
                LDSM_X4T(b[2*p][0], b[2*p][1], b[2*p+1][0], b[2*p+1][1],
                         vb + voff[p] + (uint32_t)(ks * 16 * FRS * 2));
            #pragma unroll
            for (int j = 0; j < 8; j++)
                mma_f16(accO[j], aP, b[j]);
        }

        __syncthreads();   // KV slot reads done

        // prefetch tile t+2 into slot (t&1)
        if (t + 2 < TITERS) {
            const __half* src = base + (size_t)((t + 2) * FB) * QKVW_;
            uint32_t kd = smb + (uint32_t)(K_OFF + (t & 1) * KSTG) * 2u;
            uint32_t vd = smb + (uint32_t)(V_OFF + (t & 1) * KSTG) * 2u;
            #pragma unroll
            for (int i = 0; i < 4; i++) {
                int c   = tid + 128 * i;
                int r   = c >> 3;
                int c16 = (c & 7) << 3;
                const __half* srow = src + (size_t)r * QKVW_;
                CP_ASYNC16(kd + (uint32_t)(r * FRS + c16) * 2u, srow + EMBED_ + c16);
                CP_ASYNC16(vd + (uint32_t)(r * FRS + c16) * 2u, srow + 2 * EMBED_ + c16);
            }
        }
        CP_COMMIT();
    }

    // ---- output (fp16 ctx) ----
    float inv0 = 1.0f / l0, inv1 = 1.0f / l1;
    size_t tok0 = (size_t)(bb * N_ + qt * FB + r0);
    #pragma unroll
    for (int j = 0; j < 8; j++) {
        int col = h * HD_ + j * 8 + 2 * q;
        *(__half2*)(ctx + tok0 * EMBED_ + col) =
            __floats2half2_rn(accO[j][0] * inv0, accO[j][1] * inv0);
        *(__half2*)(ctx + (tok0 + 8) * EMBED_ + col) =
            __floats2half2_rn(accO[j][2] * inv1, accO[j][3] * inv1);
    }
}

// ---------------------------------------------------------------------------
// launch
// ---------------------------------------------------------------------------
extern "C" void kernel_launch(void* const* d_in, const int* in_sizes, int n_in,
                              void* d_out, int out_size)
{
    const float* x      = (const float*)d_in[0];
    const float* ln1_g  = (const float*)d_in[1];
    const float* ln1_b  = (const float*)d_in[2];
    const float* qkv_w  = (const float*)d_in[3];
    const float* qkv_b  = (const float*)d_in[4];
    const float* proj_w = (const float*)d_in[5];
    const float* proj_b = (const float*)d_in[6];
    const float* ln2_g  = (const float*)d_in[7];
    const float* ln2_b  = (const float*)d_in[8];
    const float* fc1_w  = (const float*)d_in[9];
    const float* fc1_b  = (const float*)d_in[10];
    const float* fc2_w  = (const float*)d_in[11];
    const float* fc2_b  = (const float*)d_in[12];
    float* out = (float*)d_out;

    __half *h16, *qkv16, *ctx16, *h216, *ffn16, *wq16, *wp16, *w116, *w216;
    float *x1;
    cudaGetSymbolAddress((void**)&h16,   g_h16);
    cudaGetSymbolAddress((void**)&qkv16, g_qkv16);
    cudaGetSymbolAddress((void**)&ctx16, g_ctx16);
    cudaGetSymbolAddress((void**)&x1,    g_x1);
    cudaGetSymbolAddress((void**)&h216,  g_h216);
    cudaGetSymbolAddress((void**)&ffn16, g_ffn16);
    cudaGetSymbolAddress((void**)&wq16,  g_wq16);
    cudaGetSymbolAddress((void**)&wp16,  g_wp16);
    cudaGetSymbolAddress((void**)&w116,  g_w116);
    cudaGetSymbolAddress((void**)&w216,  g_w216);

    cudaFuncSetAttribute(flash_mma_kernel,
                         cudaFuncAttributeMaxDynamicSharedMemorySize, FLASH_SMEM);
    cudaFuncSetAttribute(mma_gemm<0>,
                         cudaFuncAttributeMaxDynamicSharedMemorySize, GEMM_DSMEM);
    cudaFuncSetAttribute(mma_gemm<1>,
                         cudaFuncAttributeMaxDynamicSharedMemorySize, GEMM_DSMEM);
    cudaFuncSetAttribute(mma_gemm<2>,
                         cudaFuncAttributeMaxDynamicSharedMemorySize, GEMM_DSMEM);

    // weights -> fp16
    {
        int n4;
        n4 = QKVW_ * EMBED_ / 4;
        f2h_kernel<<<(n4 + 255) / 256, 256>>>(qkv_w, wq16, n4);
        n4 = EMBED_ * EMBED_ / 4;
        f2h_kernel<<<(n4 + 255) / 256, 256>>>(proj_w, wp16, n4);
        n4 = HIDDEN_ * EMBED_ / 4;
        f2h_kernel<<<(n4 + 255) / 256, 256>>>(fc1_w, w116, n4);
        n4 = EMBED_ * HIDDEN_ / 4;
        f2h_kernel<<<(n4 + 255) / 256, 256>>>(fc2_w, w216, n4);
    }

    // ln1 (fp16 out)
    ln_kernel<<<TOKENS_, 256>>>(x, ln1_g, ln1_b, h16);
    // qkv = h @ qkv_w^T + b  (fp16 out)
    mma_gemm<0><<<dim3(QKVW_ / 128, TOKENS_ / 128), 128, GEMM_DSMEM>>>(
        h16, wq16, qkv_b, nullptr, qkv16, TOKENS_, QKVW_, EMBED_);
    // attention (fp16 ctx out)
    flash_mma_kernel<<<dim3(N_ / FB, B_ * HEADS_), 128, FLASH_SMEM>>>(qkv16, ctx16);
    // x1 = x + ctx @ proj_w^T + b  (fp32 out)
    mma_gemm<1><<<dim3(EMBED_ / 128, TOKENS_ / 128), 128, GEMM_DSMEM>>>(
        ctx16, wp16, proj_b, x, x1, TOKENS_, EMBED_, EMBED_);
    // ln2 (fp16 out)
    ln_kernel<<<TOKENS_, 256>>>(x1, ln2_g, ln2_b, h216);
    // ffn = gelu(h2 @ fc1_w^T + b)  (fp16 out)
    mma_gemm<2><<<dim3(HIDDEN_ / 128, TOKENS_ / 128), 128, GEMM_DSMEM>>>(
        h216, w116, fc1_b, nullptr, ffn16, TOKENS_, HIDDEN_, EMBED_);
    // out = x1 + ffn @ fc2_w^T + b  (fp32 out)
    mma_gemm<1><<<dim3(EMBED_ / 128, TOKENS_ / 128), 128, GEMM_DSMEM>>>(
        ffn16, w216, fc2_b, x1, out, TOKENS_, EMBED_, HIDDEN_);
}